// round 1
// baseline (speedup 1.0000x reference)
#include <cuda_runtime.h>

#define DN 64   // EMB_DIM
#define AN 32   // N_ANCHORS
#define ET 96   // AN + DN combined "K" dimension

// Scratch for precomputed P' = (1/A) * set_emb @ W1  [32 x 64]
__device__ float g_P[AN * DN];

// ---------------------------------------------------------------------------
// Kernel 1: tiny precompute. P'[a,d] = (1/32) * sum_e embeds[anchor[a], e] * W[e, d]
// ---------------------------------------------------------------------------
__global__ void precompute_P_kernel(const float* __restrict__ embeds,
                                    const float* __restrict__ W,     // [2D, D]
                                    const int*   __restrict__ anchorset_id) {
    int idx = blockIdx.x * blockDim.x + threadIdx.x;
    if (idx >= AN * DN) return;
    int a = idx >> 6;
    int d = idx & 63;
    long row = (long)anchorset_id[a];
    const float* erow = embeds + row * DN;
    float s = 0.0f;
#pragma unroll
    for (int e = 0; e < DN; e++) {
        s = fmaf(erow[e], W[e * DN + d], s);
    }
    g_P[idx] = s * (1.0f / (float)AN);
}

// ---------------------------------------------------------------------------
// Packed fp32x2 helpers (Blackwell f32x2 pipe; only reachable via PTX)
// ---------------------------------------------------------------------------
__device__ __forceinline__ unsigned long long pack2(float x) {
    unsigned long long r;
    asm("mov.b64 %0, {%1, %1};" : "=l"(r) : "f"(x));
    return r;
}
__device__ __forceinline__ void ffma2(unsigned long long& a,
                                      unsigned long long x,
                                      unsigned long long w) {
    asm("fma.rn.f32x2 %0, %1, %2, %0;" : "+l"(a) : "l"(x), "l"(w));
}

// ---------------------------------------------------------------------------
// Kernel 2: main pass. out[n,:] = dists[n,:] @ P' + embeds[n,:] @ W2 + b
// One thread per row. Weights in shared (all lanes broadcast-read same addr).
// ---------------------------------------------------------------------------
__global__ __launch_bounds__(128) void pnn_main_kernel(
    const float* __restrict__ embeds,   // [N, 64]
    const float* __restrict__ dists,    // [N, 32]
    const float* __restrict__ W,        // [128, 64]
    const float* __restrict__ bias,     // [64]
    float* __restrict__ out,            // [N, 64]
    int N)
{
    __shared__ float sW[ET * DN];   // rows 0..31 = P', rows 32..95 = W2
    __shared__ float sB[DN];

    for (int i = threadIdx.x; i < AN * DN; i += blockDim.x)
        sW[i] = g_P[i];
    for (int i = threadIdx.x; i < DN * DN; i += blockDim.x)
        sW[AN * DN + i] = W[DN * DN + i];   // W2 = W rows 64..127
    for (int i = threadIdx.x; i < DN; i += blockDim.x)
        sB[i] = bias[i];
    __syncthreads();

    int n = blockIdx.x * blockDim.x + threadIdx.x;
    if (n >= N) return;

    // 32 packed accumulators = 64 fp32 outputs, init to bias
    unsigned long long acc[DN / 2];
    const float2* b2 = (const float2*)sB;
#pragma unroll
    for (int j = 0; j < DN / 2; j++) {
        float2 bv = b2[j];
        asm("mov.b64 %0, {%1, %2};" : "=l"(acc[j]) : "f"(bv.x), "f"(bv.y));
    }

    const float4* drow = (const float4*)(dists  + (size_t)n * AN);
    const float4* erow = (const float4*)(embeds + (size_t)n * DN);

#pragma unroll
    for (int g = 0; g < ET / 4; g++) {           // 24 groups of 4 K-values
        float4 x4 = (g < AN / 4) ? drow[g] : erow[g - AN / 4];
#pragma unroll
        for (int k = 0; k < 4; k++) {
            int e = g * 4 + k;
            float x = (k == 0) ? x4.x : (k == 1) ? x4.y : (k == 2) ? x4.z : x4.w;
            unsigned long long x2 = pack2(x);
            const ulonglong2* wrow = (const ulonglong2*)(sW + e * DN);
#pragma unroll
            for (int j = 0; j < DN / 4; j++) {   // 16 LDS.128, broadcast
                ulonglong2 w = wrow[j];
                ffma2(acc[2 * j + 0], x2, w.x);
                ffma2(acc[2 * j + 1], x2, w.y);
            }
        }
    }

    float4* orow = (float4*)(out + (size_t)n * DN);
#pragma unroll
    for (int j = 0; j < DN / 4; j++) {
        float2 a0 = *(float2*)&acc[2 * j + 0];
        float2 a1 = *(float2*)&acc[2 * j + 1];
        orow[j] = make_float4(a0.x, a0.y, a1.x, a1.y);
    }
}

// ---------------------------------------------------------------------------
// kernel_launch: metadata order = embeds, dists_array, W_hidden, b_hidden,
// anchorset_id. Output float32 [N, 64].
// ---------------------------------------------------------------------------
extern "C" void kernel_launch(void* const* d_in, const int* in_sizes, int n_in,
                              void* d_out, int out_size) {
    const float* embeds  = (const float*)d_in[0];
    const float* dists   = (const float*)d_in[1];
    const float* W       = (const float*)d_in[2];
    const float* bias    = (const float*)d_in[3];
    const int*   anchors = (const int*)  d_in[4];

    int N = in_sizes[0] / DN;   // 100000

    precompute_P_kernel<<<(AN * DN + 255) / 256, 256>>>(embeds, W, anchors);

    int threads = 128;
    int blocks = (N + threads - 1) / threads;
    pnn_main_kernel<<<blocks, threads>>>(embeds, dists, W, bias,
                                         (float*)d_out, N);
}